// round 9
// baseline (speedup 1.0000x reference)
#include <cuda_runtime.h>
#include <math.h>

#define BATCH   8
#define NPTS    4096
#define SPLITS  16
#define SCAND   (NPTS / SPLITS)   // 256 candidates per split = one tile
#define TILE    256
#define BLOCK   64
#define Q       8                 // queries per thread
#define QPB     (BLOCK * Q)       // 512 queries per block
#define QCHUNKS_MAIN (NPTS / QPB) // 8
#define CBLOCK  128               // combine threads per block
#define QCHUNKS (NPTS / CBLOCK)   // 32 combine chunks per (dir,b)
#define NCOMBINE (QCHUNKS * BATCH * 2)  // 512 combine blocks

// Scratch (static device arrays; no allocation allowed)
__device__ unsigned long long g_pack[2 * BATCH * NPTS * SPLITS]; // (score|base) packed
__device__ float g_part[NCOMBINE];                               // per-chunk |diff|^5 sums
__device__ unsigned int g_ticket;                                // zero-init, self-resetting

// Order-preserving float -> uint32 map (monotone for all finite floats).
static __device__ __forceinline__ unsigned int fmap(float f) {
    unsigned int u = __float_as_uint(f);
    return (u & 0x80000000u) ? ~u : (u | 0x80000000u);
}
static __device__ __forceinline__ float funmap(unsigned int m) {
    return __uint_as_float((m & 0x80000000u) ? (m & 0x7FFFFFFFu) : ~m);
}

// Bit-exact rescore (identical fmaf sequence to the main loop / tile prep).
static __device__ __forceinline__ float score(float cx, float cy, float cz,
                                              float nqx, float nqy, float nqz) {
    float h = 0.5f * fmaf(cx, cx, fmaf(cy, cy, cz * cz));
    return fmaf(nqx, cx, fmaf(nqy, cy, fmaf(nqz, cz, h)));
}

// Main: each thread owns 8 queries, scans this block's 256-candidate split.
// Objective: h - q.c, h = 0.5|c|^2 (|q|^2 dropped, argmin-invariant).
// Writes one packed u64 per (query, split): [mapped score | 32-group base].
__global__ void __launch_bounds__(BLOCK) chamfer_main(
    const float* __restrict__ x, const float* __restrict__ y)
{
    const int qchunk = blockIdx.x >> 4;    // 0..7
    const int split  = blockIdx.x & 15;    // 0..15
    const int b   = blockIdx.y;
    const int dir = blockIdx.z;
    const float* q  = (dir == 0) ? x : y;
    const float* db = (dir == 0) ? y : x;
    const float* qb  = q  + (size_t)b * NPTS * 3;
    const float* dbb = db + (size_t)b * NPTS * 3;

    float nqx[Q], nqy[Q], nqz[Q];
    #pragma unroll
    for (int k = 0; k < Q; k++) {
        const int qi = qchunk * QPB + threadIdx.x + k * BLOCK;
        nqx[k] = -qb[qi*3+0];
        nqy[k] = -qb[qi*3+1];
        nqz[k] = -qb[qi*3+2];
    }

    __shared__ float4 sh[TILE];

    const int cbeg = split * SCAND;
    #pragma unroll
    for (int k = 0; k < TILE / BLOCK; k++) {
        const int cl = threadIdx.x + k * BLOCK;
        const int c  = cbeg + cl;
        float cx = dbb[c*3+0], cy = dbb[c*3+1], cz = dbb[c*3+2];
        sh[cl] = make_float4(cx, cy, cz, 0.5f * fmaf(cx, cx, fmaf(cy, cy, cz * cz)));
    }
    __syncthreads();

    float best[Q];
    int   base[Q];
    #pragma unroll
    for (int k = 0; k < Q; k++) { best[k] = 3.4e38f; base[k] = cbeg; }

    #pragma unroll
    for (int g = 0; g < TILE / 32; g++) {
        float prev[Q];
        #pragma unroll
        for (int k = 0; k < Q; k++) prev[k] = best[k];
        #pragma unroll 8
        for (int j = 0; j < 32; j++) {
            float4 c = sh[g * 32 + j];   // broadcast LDS.128, feeds 8 chains
            #pragma unroll
            for (int k = 0; k < Q; k++)
                best[k] = fminf(best[k],
                    fmaf(nqx[k], c.x, fmaf(nqy[k], c.y, fmaf(nqz[k], c.z, c.w))));
        }
        const int gb = cbeg + g * 32;
        #pragma unroll
        for (int k = 0; k < Q; k++)
            if (best[k] < prev[k]) base[k] = gb;   // strict <: earliest group wins
    }

    const int qs = (dir * BATCH + b) * NPTS;
    #pragma unroll
    for (int k = 0; k < Q; k++) {
        const int qi = qchunk * QPB + threadIdx.x + k * BLOCK;
        g_pack[(qs + qi) * SPLITS + split] =
            ((unsigned long long)fmap(best[k]) << 32) | (unsigned int)base[k];
    }
}

// Combine: branchless u64 min over 16 splits (equal score bits -> smaller base
// = earlier candidate wins), branchless descending-j rescan of the winning
// 32-group (all loads independent -> high MLP; last writer = smallest j = first
// min), gather NN, reduce sum |diff|^5 per chunk. LAST block (ticket) folds the
// final reduction and writes out[0].
__global__ void __launch_bounds__(CBLOCK) combine_kernel(
    const float* __restrict__ x, const float* __restrict__ y,
    float* __restrict__ out)
{
    const int chunk = blockIdx.x;
    const int b   = blockIdx.y;
    const int dir = blockIdx.z;
    const int qi  = chunk * CBLOCK + threadIdx.x;
    const float* q  = (dir == 0) ? x : y;
    const float* db = (dir == 0) ? y : x;
    const float* qb  = q  + (size_t)b * NPTS * 3;
    const float* dbb = db + (size_t)b * NPTS * 3;

    const int slot = ((dir * BATCH + b) * NPTS + qi) * SPLITS;
    unsigned long long w = g_pack[slot];
    #pragma unroll
    for (int s = 1; s < SPLITS; s++) {
        unsigned long long v = g_pack[slot + s];   // 16 independent LDG.64
        w = (v < w) ? v : w;
    }
    const float bb  = funmap((unsigned int)(w >> 32));
    const int  base = (int)(w & 0xFFFFFFFFu);

    const float qx = qb[qi*3+0], qy = qb[qi*3+1], qz = qb[qi*3+2];
    const float nqxv = -qx, nqyv = -qy, nqzv = -qz;

    // Branchless rescan, j descending: matches overwrite, so the final value
    // is the SMALLEST matching j = first min occurrence. No early exit ->
    // all 96 loads are independent and pipeline.
    int firstj = 0;
    #pragma unroll 8
    for (int j = 31; j >= 0; j--) {
        const int c = base + j;
        float d = score(dbb[c*3+0], dbb[c*3+1], dbb[c*3+2], nqxv, nqyv, nqzv);
        firstj = (d == bb) ? j : firstj;
    }
    const int bi = base + firstj;

    float nx = dbb[bi*3+0], ny = dbb[bi*3+1], nz = dbb[bi*3+2];
    float ax = fabsf(qx - nx), ay = fabsf(qy - ny), az = fabsf(qz - nz);
    float ax2 = ax * ax, ay2 = ay * ay, az2 = az * az;
    float v = ax2 * ax2 * ax + ay2 * ay2 * ay + az2 * az2 * az;

    __shared__ float red[CBLOCK];
    red[threadIdx.x] = v;
    __syncthreads();
    #pragma unroll
    for (int stride = CBLOCK / 2; stride >= 32; stride >>= 1) {
        if (threadIdx.x < stride) red[threadIdx.x] += red[threadIdx.x + stride];
        __syncthreads();
    }
    __shared__ bool s_last;
    if (threadIdx.x < 32) {
        float r = red[threadIdx.x];
        #pragma unroll
        for (int off = 16; off > 0; off >>= 1)
            r += __shfl_down_sync(0xFFFFFFFF, r, off);
        if (threadIdx.x == 0) {
            g_part[(dir * BATCH + b) * QCHUNKS + chunk] = r;
            __threadfence();
            unsigned int t = atomicAdd(&g_ticket, 1u);
            s_last = (t == NCOMBINE - 1);
        }
    }
    __syncthreads();

    if (s_last) {
        // Final reduction, fused into the last-arriving block.
        __shared__ float sp[NCOMBINE];
        __shared__ float roots[2 * BATCH];
        #pragma unroll
        for (int k = 0; k < NCOMBINE / CBLOCK; k++)
            sp[threadIdx.x + k * CBLOCK] = g_part[threadIdx.x + k * CBLOCK];
        __syncthreads();
        if (threadIdx.x < 2 * BATCH) {
            float s = 0.0f;
            #pragma unroll
            for (int c = 0; c < QCHUNKS; c++) s += sp[threadIdx.x * QCHUNKS + c];
            roots[threadIdx.x] = powf(s, 0.2f);
        }
        __syncthreads();
        if (threadIdx.x == 0) {
            float acc = 0.0f;
            #pragma unroll
            for (int i = 0; i < 2 * BATCH; i++) acc += roots[i];
            out[0] = acc / (float)BATCH;
            g_ticket = 0;   // reset for next graph replay (deterministic)
        }
    }
}

extern "C" void kernel_launch(void* const* d_in, const int* in_sizes, int n_in,
                              void* d_out, int out_size)
{
    const float* x = (const float*)d_in[0];
    const float* y = (const float*)d_in[1];
    float* out = (float*)d_out;

    dim3 grid(QCHUNKS_MAIN * SPLITS, BATCH, 2);   // 128 x 8 x 2 = 2048 blocks
    chamfer_main<<<grid, BLOCK>>>(x, y);

    dim3 cgrid(QCHUNKS, BATCH, 2);                // 32 x 8 x 2 = 512 blocks
    combine_kernel<<<cgrid, CBLOCK>>>(x, y, out);
}

// round 10
// speedup vs baseline: 1.4203x; 1.4203x over previous
#include <cuda_runtime.h>
#include <math.h>

#define BATCH   8
#define NPTS    4096
#define SPLITS  16
#define SCAND   (NPTS / SPLITS)   // 256 candidates per split = one tile
#define TILE    256
#define BLOCK   64
#define Q       8                 // queries per thread
#define QPB     (BLOCK * Q)       // 512 queries per block
#define QCHUNKS_MAIN (NPTS / QPB) // 8
#define CBLOCK  256               // combine threads per block
#define QCHUNKS (NPTS / CBLOCK)   // 16 combine chunks per (dir,b)
#define NCOMBINE (QCHUNKS * BATCH * 2)  // 256 combine blocks

// Scratch (static device arrays; no allocation allowed)
__device__ unsigned long long g_pack[2 * BATCH * NPTS * SPLITS]; // (score|base) packed
__device__ float g_part[NCOMBINE];                               // per-chunk |diff|^5 sums
__device__ unsigned int g_ticket;                                // zero-init, self-resetting

// Order-preserving float -> uint32 map (monotone for all finite floats).
static __device__ __forceinline__ unsigned int fmap(float f) {
    unsigned int u = __float_as_uint(f);
    return (u & 0x80000000u) ? ~u : (u | 0x80000000u);
}
static __device__ __forceinline__ float funmap(unsigned int m) {
    return __uint_as_float((m & 0x80000000u) ? (m & 0x7FFFFFFFu) : ~m);
}

// Bit-exact rescore (identical fmaf sequence everywhere it is evaluated).
static __device__ __forceinline__ float score(float cx, float cy, float cz,
                                              float nqx, float nqy, float nqz) {
    float h = 0.5f * fmaf(cx, cx, fmaf(cy, cy, cz * cz));
    return fmaf(nqx, cx, fmaf(nqy, cy, fmaf(nqz, cz, h)));
}

// Main: each thread owns 8 queries, scans this block's 256-candidate split.
// Objective: h - q.c, h = 0.5|c|^2 (|q|^2 dropped, argmin-invariant).
// Writes one packed u64 per (query, split): [mapped score | 32-group base].
__global__ void __launch_bounds__(BLOCK) chamfer_main(
    const float* __restrict__ x, const float* __restrict__ y)
{
    const int qchunk = blockIdx.x >> 4;    // 0..7
    const int split  = blockIdx.x & 15;    // 0..15
    const int b   = blockIdx.y;
    const int dir = blockIdx.z;
    const float* q  = (dir == 0) ? x : y;
    const float* db = (dir == 0) ? y : x;
    const float* qb  = q  + (size_t)b * NPTS * 3;
    const float* dbb = db + (size_t)b * NPTS * 3;

    float nqx[Q], nqy[Q], nqz[Q];
    #pragma unroll
    for (int k = 0; k < Q; k++) {
        const int qi = qchunk * QPB + threadIdx.x + k * BLOCK;
        nqx[k] = -qb[qi*3+0];
        nqy[k] = -qb[qi*3+1];
        nqz[k] = -qb[qi*3+2];
    }

    __shared__ float4 sh[TILE];

    const int cbeg = split * SCAND;
    #pragma unroll
    for (int k = 0; k < TILE / BLOCK; k++) {
        const int cl = threadIdx.x + k * BLOCK;
        const int c  = cbeg + cl;
        float cx = dbb[c*3+0], cy = dbb[c*3+1], cz = dbb[c*3+2];
        sh[cl] = make_float4(cx, cy, cz, 0.5f * fmaf(cx, cx, fmaf(cy, cy, cz * cz)));
    }
    __syncthreads();

    float best[Q];
    int   base[Q];
    #pragma unroll
    for (int k = 0; k < Q; k++) { best[k] = 3.4e38f; base[k] = cbeg; }

    #pragma unroll
    for (int g = 0; g < TILE / 32; g++) {
        float prev[Q];
        #pragma unroll
        for (int k = 0; k < Q; k++) prev[k] = best[k];
        #pragma unroll 8
        for (int j = 0; j < 32; j++) {
            float4 c = sh[g * 32 + j];   // broadcast LDS.128, feeds 8 chains
            #pragma unroll
            for (int k = 0; k < Q; k++)
                best[k] = fminf(best[k],
                    fmaf(nqx[k], c.x, fmaf(nqy[k], c.y, fmaf(nqz[k], c.z, c.w))));
        }
        const int gb = cbeg + g * 32;
        #pragma unroll
        for (int k = 0; k < Q; k++)
            if (best[k] < prev[k]) base[k] = gb;   // strict <: earliest group wins
    }

    const int qs = (dir * BATCH + b) * NPTS;
    #pragma unroll
    for (int k = 0; k < Q; k++) {
        const int qi = qchunk * QPB + threadIdx.x + k * BLOCK;
        g_pack[(qs + qi) * SPLITS + split] =
            ((unsigned long long)fmap(best[k]) << 32) | (unsigned int)base[k];
    }
}

// Combine: u64 min over 16 splits (LDG.128 x8; equal score bits -> smaller
// base = earlier candidate wins), then WARP-COOPERATIVE rescan: iteration w
// rescans lane-w's winning 32-group with lane j scoring candidate base_w+j
// (coalesced 384B per warp), ballot+ffs -> first exact match = first min.
// Then NN gather, per-chunk reduction; LAST block folds final result.
__global__ void __launch_bounds__(CBLOCK) combine_kernel(
    const float* __restrict__ x, const float* __restrict__ y,
    float* __restrict__ out)
{
    const int chunk = blockIdx.x;
    const int b   = blockIdx.y;
    const int dir = blockIdx.z;
    const int qi  = chunk * CBLOCK + threadIdx.x;
    const int lane = threadIdx.x & 31;
    const int wbase = threadIdx.x & ~31;
    const float* q  = (dir == 0) ? x : y;
    const float* db = (dir == 0) ? y : x;
    const float* qb  = q  + (size_t)b * NPTS * 3;
    const float* dbb = db + (size_t)b * NPTS * 3;

    // Split min: 16 u64 = 128 B contiguous per thread -> 8x LDG.128.
    const int slot = ((dir * BATCH + b) * NPTS + qi) * SPLITS;
    const ulonglong2* pp = reinterpret_cast<const ulonglong2*>(&g_pack[slot]);
    unsigned long long w = 0xFFFFFFFFFFFFFFFFull;
    #pragma unroll
    for (int s = 0; s < SPLITS / 2; s++) {
        ulonglong2 v = pp[s];
        unsigned long long m = (v.x < v.y) ? v.x : v.y;
        w = (m < w) ? m : w;
    }
    const float bb  = funmap((unsigned int)(w >> 32));
    const int  base = (int)(w & 0xFFFFFFFFu);

    const float qx = qb[qi*3+0], qy = qb[qi*3+1], qz = qb[qi*3+2];

    // Park per-query records in shared for cheap intra-warp broadcast.
    __shared__ float4 sQ[CBLOCK];   // (nqx, nqy, nqz, bb)
    __shared__ int    sB[CBLOCK];   // base
    sQ[threadIdx.x] = make_float4(-qx, -qy, -qz, bb);
    sB[threadIdx.x] = base;
    __syncwarp();

    int bi = base;
    #pragma unroll 4
    for (int ws = 0; ws < 32; ws++) {
        const float4 r  = sQ[wbase + ws];   // LDS.128 broadcast
        const int    bw = sB[wbase + ws];   // LDS broadcast
        const int c = bw + lane;
        // Coalesced: warp covers candidates bw..bw+31 (384 contiguous bytes).
        float d = score(dbb[c*3+0], dbb[c*3+1], dbb[c*3+2], r.x, r.y, r.z);
        unsigned int mask = __ballot_sync(0xFFFFFFFFu, d == r.w);
        // mask != 0 guaranteed (bit-exact recompute). Smallest j = first min.
        if (lane == ws) bi = bw + (__ffs(mask) - 1);
    }

    float nx = dbb[bi*3+0], ny = dbb[bi*3+1], nz = dbb[bi*3+2];
    float ax = fabsf(qx - nx), ay = fabsf(qy - ny), az = fabsf(qz - nz);
    float ax2 = ax * ax, ay2 = ay * ay, az2 = az * az;
    float v = ax2 * ax2 * ax + ay2 * ay2 * ay + az2 * az2 * az;

    __shared__ float red[CBLOCK];
    red[threadIdx.x] = v;
    __syncthreads();
    #pragma unroll
    for (int stride = CBLOCK / 2; stride >= 32; stride >>= 1) {
        if (threadIdx.x < stride) red[threadIdx.x] += red[threadIdx.x + stride];
        __syncthreads();
    }
    __shared__ bool s_last;
    if (threadIdx.x < 32) {
        float r = red[threadIdx.x];
        #pragma unroll
        for (int off = 16; off > 0; off >>= 1)
            r += __shfl_down_sync(0xFFFFFFFF, r, off);
        if (threadIdx.x == 0) {
            g_part[(dir * BATCH + b) * QCHUNKS + chunk] = r;
            __threadfence();
            unsigned int t = atomicAdd(&g_ticket, 1u);
            s_last = (t == NCOMBINE - 1);
        }
    }
    __syncthreads();

    if (s_last) {
        // Final reduction, fused into the last-arriving block.
        __shared__ float sp[NCOMBINE];
        __shared__ float roots[2 * BATCH];
        sp[threadIdx.x] = g_part[threadIdx.x];
        __syncthreads();
        if (threadIdx.x < 2 * BATCH) {
            float s = 0.0f;
            #pragma unroll
            for (int c = 0; c < QCHUNKS; c++) s += sp[threadIdx.x * QCHUNKS + c];
            roots[threadIdx.x] = powf(s, 0.2f);
        }
        __syncthreads();
        if (threadIdx.x == 0) {
            float acc = 0.0f;
            #pragma unroll
            for (int i = 0; i < 2 * BATCH; i++) acc += roots[i];
            out[0] = acc / (float)BATCH;
            g_ticket = 0;   // reset for next graph replay (deterministic)
        }
    }
}

extern "C" void kernel_launch(void* const* d_in, const int* in_sizes, int n_in,
                              void* d_out, int out_size)
{
    const float* x = (const float*)d_in[0];
    const float* y = (const float*)d_in[1];
    float* out = (float*)d_out;

    dim3 grid(QCHUNKS_MAIN * SPLITS, BATCH, 2);   // 128 x 8 x 2 = 2048 blocks
    chamfer_main<<<grid, BLOCK>>>(x, y);

    dim3 cgrid(QCHUNKS, BATCH, 2);                // 16 x 8 x 2 = 256 blocks
    combine_kernel<<<cgrid, CBLOCK>>>(x, y, out);
}